// round 1
// baseline (speedup 1.0000x reference)
#include <cuda_runtime.h>
#include <cstdint>
#include <math.h>

#define BB 16
#define HH 768
#define WW 768
#define NPIX (HH*WW)
#define TOPK 100
#define NP 4
#define NPATCH (BB*NP)   // 64
#define PS 64            // patch size

// ---------------- scratch (static device globals; no allocation allowed) ----
__device__ float g_mask[BB*NPIX];        // detector mask, later final window
__device__ float g_tmp[BB*NPIX];         // horizontal pool intermediate
__device__ unsigned g_hist[BB][256];
__device__ unsigned g_prefix[BB];
__device__ int g_K[BB];
__device__ int g_cntA[BB];
__device__ int g_cntB[BB];
__device__ unsigned long long g_listA[BB][128];
__device__ int g_listB[BB][16384];
__device__ int g_topidx[BB][TOPK];
__device__ int g_py[NPATCH], g_px[NPATCH];
__device__ float g_patches[NPATCH*3*PS*PS];
__device__ float g_act1[NPATCH*64*32*32];
__device__ float g_act2[NPATCH*128*16*16];
__device__ float g_act3[NPATCH*256*8*8];
__device__ float g_act4[NPATCH*512*4*4];
__device__ float g_logits[NPATCH];
__device__ float g_bnscale[512], g_bnshift[512];

// ---------------- detector ----------------
__global__ void detector_kernel(const float* __restrict__ src) {
    long long total = (long long)BB*NPIX;
    for (long long idx = (long long)blockIdx.x*blockDim.x + threadIdx.x;
         idx < total; idx += (long long)gridDim.x*blockDim.x) {
        int b = (int)(idx / NPIX);
        int p = (int)(idx % NPIX);
        const float* sb = src + (size_t)b*3*NPIX;
        float r  = (sb[p]          + 1.f)*0.5f;
        float gg = (sb[NPIX + p]   + 1.f)*0.5f;
        float bl = (sb[2*NPIX + p] + 1.f)*0.5f;
        float br = 0.299f*r + 0.587f*gg + 0.114f*bl;
        float bm = 1.f/(1.f + expf(-20.f*(br - 0.65f)));
        float mx = fmaxf(r, fmaxf(gg, bl));
        float mn = fminf(r, fminf(gg, bl));
        float ls = 1.f/(1.f + expf(-20.f*(0.15f - (mx - mn))));
        g_mask[idx] = bm*ls;
    }
}

// ---------------- 15-tap horizontal sum (zero pad) ----------------
__global__ void hpool_kernel() {
    __shared__ float row[WW + 14];
    int y = blockIdx.x, b = blockIdx.y;
    const float* ip = g_mask + ((size_t)b*HH + y)*WW;
    for (int i = threadIdx.x; i < WW + 14; i += blockDim.x) {
        int x = i - 7;
        row[i] = (x >= 0 && x < WW) ? ip[x] : 0.f;
    }
    __syncthreads();
    float* op = g_tmp + ((size_t)b*HH + y)*WW;
    for (int x = threadIdx.x; x < WW; x += blockDim.x) {
        float s = 0.f;
        #pragma unroll
        for (int d = 0; d < 15; d++) s += row[x + d];
        op[x] = s;
    }
}

// ---------------- 15-tap vertical sum + /225, writes back to g_mask --------
__global__ void vpool_kernel() {
    __shared__ float tile[78][32];
    int c0 = blockIdx.x*32, r0 = blockIdx.y*64, b = blockIdx.z;
    const float* ip = g_tmp + (size_t)b*NPIX;
    for (int i = threadIdx.x; i < 78*32; i += blockDim.x) {
        int r = i >> 5, c = i & 31;
        int y = r0 + r - 7;
        tile[r][c] = (y >= 0 && y < HH) ? ip[(size_t)y*WW + c0 + c] : 0.f;
    }
    __syncthreads();
    float* op = g_mask + (size_t)b*NPIX;
    int c = threadIdx.x & 31;
    for (int rr = threadIdx.x >> 5; rr < 64; rr += blockDim.x >> 5) {
        float s = 0.f;
        #pragma unroll
        for (int d = 0; d < 15; d++) s += tile[rr + d][c];
        op[(size_t)(r0 + rr)*WW + c0 + c] = s / 225.0f;
    }
}

// ---------------- exact top-100 via MSB radix select ----------------
__global__ void topk_init_kernel() {
    int t = threadIdx.x;
    if (t < BB) { g_prefix[t] = 0u; g_K[t] = TOPK; g_cntA[t] = 0; g_cntB[t] = 0; }
    for (int i = t; i < BB*256; i += blockDim.x) ((unsigned*)g_hist)[i] = 0u;
}

__global__ void topk_hist_kernel(int digit) {
    int b = blockIdx.y;
    __shared__ unsigned sh[256];
    for (int i = threadIdx.x; i < 256; i += blockDim.x) sh[i] = 0u;
    __syncthreads();
    unsigned pref  = g_prefix[b];
    unsigned hmask = (digit == 3) ? 0u : (0xFFFFFFFFu << ((digit + 1)*8));
    const float* wp = g_mask + (size_t)b*NPIX;
    for (int i = blockIdx.x*blockDim.x + threadIdx.x; i < NPIX; i += gridDim.x*blockDim.x) {
        unsigned key = __float_as_uint(wp[i]);
        if ((key & hmask) == (pref & hmask))
            atomicAdd(&sh[(key >> (digit*8)) & 255u], 1u);
    }
    __syncthreads();
    for (int i = threadIdx.x; i < 256; i += blockDim.x)
        if (sh[i]) atomicAdd(&g_hist[b][i], sh[i]);
}

__global__ void topk_resolve_kernel(int digit) {
    int b = threadIdx.x;
    if (b < BB) {
        int K = g_K[b];
        unsigned acc = 0;
        int bin = 0;
        for (int j = 255; j >= 0; j--) {
            unsigned c = g_hist[b][j];
            if (acc + c >= (unsigned)K) { bin = j; break; }
            acc += c;
        }
        g_prefix[b] |= ((unsigned)bin) << (digit*8);
        g_K[b] = K - (int)acc;
    }
    __syncthreads();
    for (int i = threadIdx.x; i < BB*256; i += blockDim.x) ((unsigned*)g_hist)[i] = 0u;
}

__global__ void topk_collect_kernel() {
    int b = blockIdx.y;
    unsigned T = g_prefix[b];
    const float* wp = g_mask + (size_t)b*NPIX;
    for (int i = blockIdx.x*blockDim.x + threadIdx.x; i < NPIX; i += gridDim.x*blockDim.x) {
        unsigned key = __float_as_uint(wp[i]);
        if (key > T) {
            int p = atomicAdd(&g_cntA[b], 1);
            if (p < 128)
                g_listA[b][p] = ((unsigned long long)key << 32) | (unsigned)(0xFFFFFFFFu - (unsigned)i);
        } else if (key == T) {
            int p = atomicAdd(&g_cntB[b], 1);
            if (p < 16384) g_listB[b][p] = i;
        }
    }
}

__global__ void topk_final_kernel() {
    int b = blockIdx.x;
    int tid = threadIdx.x;                // 128 threads
    __shared__ unsigned long long A[128];
    int G = g_cntA[b]; if (G > 99) G = 99;
    if (tid == 0) {
        for (int i = 0; i < G; i++) A[i] = g_listA[b][i];
        for (int i = 1; i < G; i++) {     // insertion sort, descending
            unsigned long long v = A[i]; int j = i - 1;
            while (j >= 0 && A[j] < v) { A[j+1] = A[j]; j--; }
            A[j+1] = v;
        }
        for (int i = 0; i < G; i++)
            g_topidx[b][i] = (int)(0xFFFFFFFFu - (unsigned)(A[i] & 0xFFFFFFFFu));
    }
    __syncthreads();
    int m  = TOPK - G;
    int nB = min(g_cntB[b], 16384);
    __shared__ int smin[128];
    for (int k = 0; k < m; k++) {
        int lmin = 0x7FFFFFFF;
        for (int i = tid; i < nB; i += 128) { int v = g_listB[b][i]; if (v < lmin) lmin = v; }
        smin[tid] = lmin; __syncthreads();
        for (int s = 64; s > 0; s >>= 1) { if (tid < s) smin[tid] = min(smin[tid], smin[tid + s]); __syncthreads(); }
        int mv = smin[0];
        __syncthreads();
        if (tid == 0) g_topidx[b][G + k] = mv;
        for (int i = tid; i < nB; i += 128) if (g_listB[b][i] == mv) g_listB[b][i] = 0x7FFFFFFF;
        __syncthreads();
    }
}

// ---------------- patch coords + gather ----------------
__global__ void coords_kernel(const int* __restrict__ rand_sel) {
    int t = threadIdx.x;
    if (t >= NPATCH) return;
    int b = t >> 2;
    int r = rand_sel[t];
    int sel = g_topidx[b][r];
    int y = sel / WW - PS/2; y = max(0, min(y, HH - PS));
    int x = sel % WW - PS/2; x = max(0, min(x, WW - PS));
    g_py[t] = y; g_px[t] = x;
}

__global__ void gather_kernel(const float* __restrict__ pred) {
    int idx = blockIdx.x*blockDim.x + threadIdx.x;
    const int total = NPATCH*3*PS*PS;
    if (idx >= total) return;
    int j = idx & 63; int t = idx >> 6;
    int i = t & 63;   t >>= 6;
    int c = t % 3;    int p = t / 3;
    int b = p >> 2;
    g_patches[idx] = pred[(((size_t)b*3 + c)*HH + g_py[p] + i)*WW + g_px[p] + j];
}

// ---------------- direct conv: k4, s2, p1; weights staged in smem ---------
template<int IC, bool LRELU>
__global__ void conv_s2_kernel(const float* __restrict__ in, const float* __restrict__ w,
                               const float* __restrict__ bias, float* __restrict__ out,
                               int N, int OC, int IH, int IW, int OH, int OW) {
    __shared__ float sw[IC*16];
    int oc = blockIdx.y;
    for (int i = threadIdx.x; i < IC*16; i += blockDim.x) sw[i] = w[(size_t)oc*IC*16 + i];
    __syncthreads();
    int idx = blockIdx.x*blockDim.x + threadIdx.x;
    int total = N*OH*OW;
    if (idx >= total) return;
    int ow = idx % OW; int t = idx / OW;
    int oh = t % OH;   int n = t / OH;
    const float* ib = in + (size_t)n*IC*IH*IW;
    float acc = bias[oc];
    int ih0 = oh*2 - 1, iw0 = ow*2 - 1;
    for (int ic = 0; ic < IC; ic++) {
        const float* ip = ib + (size_t)ic*IH*IW;
        const float* wp = sw + ic*16;
        #pragma unroll
        for (int kh = 0; kh < 4; kh++) {
            int ih = ih0 + kh;
            if ((unsigned)ih < (unsigned)IH) {
                const float* rp = ip + (size_t)ih*IW;
                #pragma unroll
                for (int kw = 0; kw < 4; kw++) {
                    int iw = iw0 + kw;
                    if ((unsigned)iw < (unsigned)IW)
                        acc += rp[iw] * wp[kh*4 + kw];
                }
            }
        }
    }
    if (LRELU) acc = acc > 0.f ? acc : 0.2f*acc;
    out[((size_t)(n*OC + oc)*OH + oh)*OW + ow] = acc;
}

// ---------------- batchnorm: stats (double accum) then fused apply+lrelu ---
__global__ void bn_reduce_kernel(const float* __restrict__ x, const float* __restrict__ g,
                                 const float* __restrict__ be, int N, int C, int S) {
    int c = blockIdx.x;
    double s = 0.0, s2 = 0.0;
    int M = N*S;
    for (int j = threadIdx.x; j < M; j += blockDim.x) {
        int n = j / S, sp = j % S;
        float v = x[((size_t)n*C + c)*S + sp];
        s += (double)v; s2 += (double)v*(double)v;
    }
    __shared__ double sh[256], sh2[256];
    sh[threadIdx.x] = s; sh2[threadIdx.x] = s2; __syncthreads();
    for (int st = 128; st > 0; st >>= 1) {
        if (threadIdx.x < st) { sh[threadIdx.x] += sh[threadIdx.x+st]; sh2[threadIdx.x] += sh2[threadIdx.x+st]; }
        __syncthreads();
    }
    if (threadIdx.x == 0) {
        double mean = sh[0] / M;
        double var  = sh2[0] / M - mean*mean;
        double isd  = 1.0 / sqrt(var + 1e-5);
        float sc = (float)((double)g[c] * isd);
        g_bnscale[c] = sc;
        g_bnshift[c] = be[c] - (float)(mean * (double)sc);
    }
}

__global__ void bn_apply_kernel(float* __restrict__ x, int C, int S, int total) {
    for (int idx = blockIdx.x*blockDim.x + threadIdx.x; idx < total; idx += gridDim.x*blockDim.x) {
        int c = (idx / S) % C;
        float v = x[idx]*g_bnscale[c] + g_bnshift[c];
        x[idx] = v > 0.f ? v : 0.2f*v;
    }
}

// ---------------- conv5 (dot product per patch) + loss ----------------
__global__ void conv5_kernel(const float* __restrict__ in, const float* __restrict__ w,
                             const float* __restrict__ b5) {
    int n = blockIdx.x, tid = threadIdx.x;
    const float* ip = in + (size_t)n*8192;
    float s = 0.f;
    for (int i = tid; i < 8192; i += 256) s += ip[i]*w[i];
    __shared__ float sh[256];
    sh[tid] = s; __syncthreads();
    for (int st = 128; st > 0; st >>= 1) { if (tid < st) sh[tid] += sh[tid+st]; __syncthreads(); }
    if (tid == 0) g_logits[n] = sh[0] + b5[0];
}

__global__ void loss_kernel(float* __restrict__ out) {
    int tid = threadIdx.x;   // 64
    float x = -g_logits[tid];
    float sp = fmaxf(x, 0.f) + log1pf(expf(-fabsf(x)));
    __shared__ float sh[64];
    sh[tid] = sp; __syncthreads();
    for (int s = 32; s > 0; s >>= 1) { if (tid < s) sh[tid] += sh[tid+s]; __syncthreads(); }
    if (tid == 0) out[0] = sh[0] / 64.f;
}

// ---------------- launcher ----------------
extern "C" void kernel_launch(void* const* d_in, const int* in_sizes, int n_in,
                              void* d_out, int out_size) {
    const float* pred     = (const float*)d_in[0];
    const float* source   = (const float*)d_in[1];
    const int*   rand_sel = (const int*)d_in[2];
    const float* w1 = (const float*)d_in[3];  const float* b1 = (const float*)d_in[4];
    const float* w2 = (const float*)d_in[5];  const float* b2 = (const float*)d_in[6];
    const float* g2 = (const float*)d_in[7];  const float* be2= (const float*)d_in[8];
    const float* w3 = (const float*)d_in[9];  const float* b3 = (const float*)d_in[10];
    const float* g3 = (const float*)d_in[11]; const float* be3= (const float*)d_in[12];
    const float* w4 = (const float*)d_in[13]; const float* b4 = (const float*)d_in[14];
    const float* g4 = (const float*)d_in[15]; const float* be4= (const float*)d_in[16];
    const float* w5 = (const float*)d_in[17]; const float* b5 = (const float*)d_in[18];
    float* out = (float*)d_out;

    float *patches, *a1, *a2, *a3, *a4;
    cudaGetSymbolAddress((void**)&patches, g_patches);
    cudaGetSymbolAddress((void**)&a1, g_act1);
    cudaGetSymbolAddress((void**)&a2, g_act2);
    cudaGetSymbolAddress((void**)&a3, g_act3);
    cudaGetSymbolAddress((void**)&a4, g_act4);

    // 1. detector mask
    detector_kernel<<<8192, 256>>>(source);
    // 2. 15x15 avg pool (separable)
    hpool_kernel<<<dim3(HH, BB), 256>>>();
    vpool_kernel<<<dim3(WW/32, HH/64, BB), 256>>>();
    // 3. exact per-image top-100 (radix select)
    topk_init_kernel<<<1, 256>>>();
    for (int d = 3; d >= 0; d--) {
        topk_hist_kernel<<<dim3(48, BB), 256>>>(d);
        topk_resolve_kernel<<<1, 256>>>(d);
    }
    topk_collect_kernel<<<dim3(48, BB), 256>>>();
    topk_final_kernel<<<BB, 128>>>();
    // 4. patch coords + gather
    coords_kernel<<<1, 64>>>(rand_sel);
    gather_kernel<<<(NPATCH*3*PS*PS + 255)/256, 256>>>(pred);
    // 5. discriminator
    conv_s2_kernel<3,  true ><<<dim3((NPATCH*32*32 + 255)/256,  64), 256>>>(patches, w1, b1, a1, NPATCH,  64, 64, 64, 32, 32);
    conv_s2_kernel<64, false><<<dim3((NPATCH*16*16 + 255)/256, 128), 256>>>(a1, w2, b2, a2, NPATCH, 128, 32, 32, 16, 16);
    bn_reduce_kernel<<<128, 256>>>(a2, g2, be2, NPATCH, 128, 16*16);
    bn_apply_kernel<<<1024, 256>>>(a2, 128, 16*16, NPATCH*128*16*16);
    conv_s2_kernel<128,false><<<dim3((NPATCH*8*8 + 255)/256, 256), 256>>>(a2, w3, b3, a3, NPATCH, 256, 16, 16, 8, 8);
    bn_reduce_kernel<<<256, 256>>>(a3, g3, be3, NPATCH, 256, 8*8);
    bn_apply_kernel<<<512, 256>>>(a3, 256, 8*8, NPATCH*256*8*8);
    conv_s2_kernel<256,false><<<dim3((NPATCH*4*4 + 255)/256, 512), 256>>>(a3, w4, b4, a4, NPATCH, 512, 8, 8, 4, 4);
    bn_reduce_kernel<<<512, 256>>>(a4, g4, be4, NPATCH, 512, 4*4);
    bn_apply_kernel<<<256, 256>>>(a4, 512, 4*4, NPATCH*512*4*4);
    conv5_kernel<<<NPATCH, 256>>>(a4, w5, b5);
    // 6. loss
    loss_kernel<<<1, 64>>>(out);
}

// round 2
// speedup vs baseline: 3.3117x; 3.3117x over previous
#include <cuda_runtime.h>
#include <cstdint>
#include <math.h>

#define BB 16
#define HH 768
#define WW 768
#define NPIX (HH*WW)
#define TOPK 100
#define NP 4
#define NPATCH (BB*NP)   // 64
#define PS 64            // patch size

// ---------------- scratch (static device globals; no allocation allowed) ----
__device__ float g_mask[BB*NPIX];        // detector mask, later final window
__device__ float g_tmp[BB*NPIX];         // horizontal pool intermediate
__device__ unsigned g_hist[BB][256];
__device__ unsigned g_prefix[BB];
__device__ int g_K[BB];
__device__ int g_cntA[BB];
__device__ int g_cntB[BB];
__device__ unsigned long long g_listA[BB][128];
__device__ int g_listB[BB][16384];
__device__ int g_topidx[BB][TOPK];
__device__ int g_py[NPATCH], g_px[NPATCH];
__device__ float g_patches[NPATCH*3*PS*PS];
__device__ float g_act1[NPATCH*64*32*32];
__device__ float g_act2[NPATCH*128*16*16];
__device__ float g_act3[NPATCH*256*8*8];
__device__ float g_act4[NPATCH*512*4*4];
__device__ float g_logits[NPATCH];
__device__ float g_bnscale[512], g_bnshift[512];
// K-major transposed weights
__device__ float g_wT1[48*64];
__device__ float g_wT2[1024*128];
__device__ float g_wT3[2048*256];
__device__ float g_wT4[4096*512];

// ---------------- detector ----------------
__global__ void detector_kernel(const float* __restrict__ src) {
    long long total = (long long)BB*NPIX;
    for (long long idx = (long long)blockIdx.x*blockDim.x + threadIdx.x;
         idx < total; idx += (long long)gridDim.x*blockDim.x) {
        int b = (int)(idx / NPIX);
        int p = (int)(idx % NPIX);
        const float* sb = src + (size_t)b*3*NPIX;
        float r  = (sb[p]          + 1.f)*0.5f;
        float gg = (sb[NPIX + p]   + 1.f)*0.5f;
        float bl = (sb[2*NPIX + p] + 1.f)*0.5f;
        float br = 0.299f*r + 0.587f*gg + 0.114f*bl;
        float bm = 1.f/(1.f + expf(-20.f*(br - 0.65f)));
        float mx = fmaxf(r, fmaxf(gg, bl));
        float mn = fminf(r, fminf(gg, bl));
        float ls = 1.f/(1.f + expf(-20.f*(0.15f - (mx - mn))));
        g_mask[idx] = bm*ls;
    }
}

// ---------------- 15-tap horizontal sum (zero pad) ----------------
__global__ void hpool_kernel() {
    __shared__ float row[WW + 14];
    int y = blockIdx.x, b = blockIdx.y;
    const float* ip = g_mask + ((size_t)b*HH + y)*WW;
    for (int i = threadIdx.x; i < WW + 14; i += blockDim.x) {
        int x = i - 7;
        row[i] = (x >= 0 && x < WW) ? ip[x] : 0.f;
    }
    __syncthreads();
    float* op = g_tmp + ((size_t)b*HH + y)*WW;
    for (int x = threadIdx.x; x < WW; x += blockDim.x) {
        float s = 0.f;
        #pragma unroll
        for (int d = 0; d < 15; d++) s += row[x + d];
        op[x] = s;
    }
}

// ---------------- 15-tap vertical sum + /225, writes back to g_mask --------
__global__ void vpool_kernel() {
    __shared__ float tile[78][32];
    int c0 = blockIdx.x*32, r0 = blockIdx.y*64, b = blockIdx.z;
    const float* ip = g_tmp + (size_t)b*NPIX;
    for (int i = threadIdx.x; i < 78*32; i += blockDim.x) {
        int r = i >> 5, c = i & 31;
        int y = r0 + r - 7;
        tile[r][c] = (y >= 0 && y < HH) ? ip[(size_t)y*WW + c0 + c] : 0.f;
    }
    __syncthreads();
    float* op = g_mask + (size_t)b*NPIX;
    int c = threadIdx.x & 31;
    for (int rr = threadIdx.x >> 5; rr < 64; rr += blockDim.x >> 5) {
        float s = 0.f;
        #pragma unroll
        for (int d = 0; d < 15; d++) s += tile[rr + d][c];
        op[(size_t)(r0 + rr)*WW + c0 + c] = s / 225.0f;
    }
}

// ---------------- exact top-100 via MSB radix select ----------------
__global__ void topk_init_kernel() {
    int t = threadIdx.x;
    if (t < BB) { g_prefix[t] = 0u; g_K[t] = TOPK; g_cntA[t] = 0; g_cntB[t] = 0; }
    for (int i = t; i < BB*256; i += blockDim.x) ((unsigned*)g_hist)[i] = 0u;
}

__global__ void topk_hist_kernel(int digit) {
    int b = blockIdx.y;
    __shared__ unsigned sh[256];
    for (int i = threadIdx.x; i < 256; i += blockDim.x) sh[i] = 0u;
    __syncthreads();
    unsigned pref  = g_prefix[b];
    unsigned hmask = (digit == 3) ? 0u : (0xFFFFFFFFu << ((digit + 1)*8));
    const float* wp = g_mask + (size_t)b*NPIX;
    for (int i = blockIdx.x*blockDim.x + threadIdx.x; i < NPIX; i += gridDim.x*blockDim.x) {
        unsigned key = __float_as_uint(wp[i]);
        if ((key & hmask) == (pref & hmask))
            atomicAdd(&sh[(key >> (digit*8)) & 255u], 1u);
    }
    __syncthreads();
    for (int i = threadIdx.x; i < 256; i += blockDim.x)
        if (sh[i]) atomicAdd(&g_hist[b][i], sh[i]);
}

__global__ void topk_resolve_kernel(int digit) {
    int b = threadIdx.x;
    if (b < BB) {
        int K = g_K[b];
        unsigned acc = 0;
        int bin = 0;
        for (int j = 255; j >= 0; j--) {
            unsigned c = g_hist[b][j];
            if (acc + c >= (unsigned)K) { bin = j; break; }
            acc += c;
        }
        g_prefix[b] |= ((unsigned)bin) << (digit*8);
        g_K[b] = K - (int)acc;
    }
    __syncthreads();
    for (int i = threadIdx.x; i < BB*256; i += blockDim.x) ((unsigned*)g_hist)[i] = 0u;
}

__global__ void topk_collect_kernel() {
    int b = blockIdx.y;
    unsigned T = g_prefix[b];
    const float* wp = g_mask + (size_t)b*NPIX;
    for (int i = blockIdx.x*blockDim.x + threadIdx.x; i < NPIX; i += gridDim.x*blockDim.x) {
        unsigned key = __float_as_uint(wp[i]);
        if (key > T) {
            int p = atomicAdd(&g_cntA[b], 1);
            if (p < 128)
                g_listA[b][p] = ((unsigned long long)key << 32) | (unsigned)(0xFFFFFFFFu - (unsigned)i);
        } else if (key == T) {
            int p = atomicAdd(&g_cntB[b], 1);
            if (p < 16384) g_listB[b][p] = i;
        }
    }
}

__global__ void topk_final_kernel() {
    int b = blockIdx.x;
    int tid = threadIdx.x;                // 128 threads
    __shared__ unsigned long long A[128];
    int G = g_cntA[b]; if (G > 99) G = 99;
    if (tid == 0) {
        for (int i = 0; i < G; i++) A[i] = g_listA[b][i];
        for (int i = 1; i < G; i++) {     // insertion sort, descending
            unsigned long long v = A[i]; int j = i - 1;
            while (j >= 0 && A[j] < v) { A[j+1] = A[j]; j--; }
            A[j+1] = v;
        }
        for (int i = 0; i < G; i++)
            g_topidx[b][i] = (int)(0xFFFFFFFFu - (unsigned)(A[i] & 0xFFFFFFFFu));
    }
    __syncthreads();
    int m  = TOPK - G;
    int nB = min(g_cntB[b], 16384);
    __shared__ int smin[128];
    for (int k = 0; k < m; k++) {
        int lmin = 0x7FFFFFFF;
        for (int i = tid; i < nB; i += 128) { int v = g_listB[b][i]; if (v < lmin) lmin = v; }
        smin[tid] = lmin; __syncthreads();
        for (int s = 64; s > 0; s >>= 1) { if (tid < s) smin[tid] = min(smin[tid], smin[tid + s]); __syncthreads(); }
        int mv = smin[0];
        __syncthreads();
        if (tid == 0) g_topidx[b][G + k] = mv;
        for (int i = tid; i < nB; i += 128) if (g_listB[b][i] == mv) g_listB[b][i] = 0x7FFFFFFF;
        __syncthreads();
    }
}

// ---------------- patch coords + gather ----------------
__global__ void coords_kernel(const int* __restrict__ rand_sel) {
    int t = threadIdx.x;
    if (t >= NPATCH) return;
    int b = t >> 2;
    int r = rand_sel[t];
    int sel = g_topidx[b][r];
    int y = sel / WW - PS/2; y = max(0, min(y, HH - PS));
    int x = sel % WW - PS/2; x = max(0, min(x, WW - PS));
    g_py[t] = y; g_px[t] = x;
}

__global__ void gather_kernel(const float* __restrict__ pred) {
    int idx = blockIdx.x*blockDim.x + threadIdx.x;
    const int total = NPATCH*3*PS*PS;
    if (idx >= total) return;
    int j = idx & 63; int t = idx >> 6;
    int i = t & 63;   t >>= 6;
    int c = t % 3;    int p = t / 3;
    int b = p >> 2;
    g_patches[idx] = pred[(((size_t)b*3 + c)*HH + g_py[p] + i)*WW + g_px[p] + j];
}

// ---------------- weight transpose: w[OC][K] -> wT[K][OC] ----------------
__global__ void wtrans_kernel(const float* __restrict__ w, float* __restrict__ wT,
                              int OC, int K) {
    int i = blockIdx.x*blockDim.x + threadIdx.x;
    if (i < OC*K) {
        int oc = i / K, k = i % K;
        wT[(size_t)k*OC + oc] = w[i];
    }
}

// ---------------- implicit-GEMM conv: k4 s2 p1 --------------------------
// C[M,N]: M = NPATCH*OH*OW (spatial-major rows), N = OC.
// A[m,k] = im2col(input), k = ic*16 + kh*4 + kw.  B = wT (K x OC, K-major).
// BM=BN=64, BK=16, 256 threads, 4x4 micro-tile, double-buffered smem.
template<int IC, int LOG_OW, bool LRELU>
__global__ __launch_bounds__(256) void conv_gemm_kernel(
        const float* __restrict__ in, const float* __restrict__ wT,
        const float* __restrict__ bias, float* __restrict__ out, int K) {
    constexpr int OW  = 1 << LOG_OW;
    constexpr int OHW = OW*OW;
    constexpr int IW  = 2*OW;
    constexpr int IH  = IW;
    __shared__ __align__(16) float As[2][16][68];
    __shared__ __align__(16) float Bs[2][16][68];

    const int tid = threadIdx.x;
    const int m0  = blockIdx.x << 6;
    const int n0  = blockIdx.y << 6;
    const int OCt = gridDim.y << 6;

    // A-load mapping: thread -> (row lm, k-quad kq)
    const int lm = tid >> 2;          // 0..63
    const int kq = (tid & 3) << 2;    // 0,4,8,12
    const int am   = m0 + lm;
    const int nimg = am >> (2*LOG_OW);
    const int arem = am & (OHW-1);
    const int ih0  = ((arem >> LOG_OW) << 1) - 1;
    const int iw0  = ((arem & (OW-1)) << 1) - 1;
    const float* ibase = in + (size_t)nimg*IC*IH*IW;

    // B-load mapping
    const int bk = tid >> 4;          // 0..15
    const int bn = (tid & 15) << 2;

    // compute micro-tile mapping
    const int tm = (tid >> 4) << 2;
    const int tn = (tid & 15) << 2;

    float acc[4][4] = {};
    float pa[4];
    float4 pb;

    auto loadA = [&](int k0) {
        int k  = k0 + kq;
        int ic = k >> 4;
        int ih = ih0 + ((k >> 2) & 3);
        const float* rp = ibase + ((size_t)ic*IH + ih)*IW;
        bool rowok = (unsigned)ih < (unsigned)IH;
        #pragma unroll
        for (int j = 0; j < 4; j++) {
            int iw = iw0 + j;
            pa[j] = (rowok && (unsigned)iw < (unsigned)IW) ? __ldg(rp + iw) : 0.f;
        }
    };
    auto loadB = [&](int k0) {
        pb = *(const float4*)&wT[(size_t)(k0 + bk)*OCt + n0 + bn];
    };
    auto stsA = [&](int buf) {
        #pragma unroll
        for (int j = 0; j < 4; j++) As[buf][kq+j][lm] = pa[j];
    };
    auto stsB = [&](int buf) {
        *(float4*)&Bs[buf][bk][bn] = pb;
    };

    loadA(0); loadB(0);
    stsA(0); stsB(0);
    __syncthreads();

    const int nch = K >> 4;
    for (int ch = 0; ch < nch; ch++) {
        int cur = ch & 1;
        if (ch + 1 < nch) { loadA((ch+1) << 4); loadB((ch+1) << 4); }
        #pragma unroll
        for (int k = 0; k < 16; k++) {
            float4 a = *(const float4*)&As[cur][k][tm];
            float4 b = *(const float4*)&Bs[cur][k][tn];
            acc[0][0] += a.x*b.x; acc[0][1] += a.x*b.y; acc[0][2] += a.x*b.z; acc[0][3] += a.x*b.w;
            acc[1][0] += a.y*b.x; acc[1][1] += a.y*b.y; acc[1][2] += a.y*b.z; acc[1][3] += a.y*b.w;
            acc[2][0] += a.z*b.x; acc[2][1] += a.z*b.y; acc[2][2] += a.z*b.z; acc[2][3] += a.z*b.w;
            acc[3][0] += a.w*b.x; acc[3][1] += a.w*b.y; acc[3][2] += a.w*b.z; acc[3][3] += a.w*b.w;
        }
        if (ch + 1 < nch) {
            stsA(cur ^ 1); stsB(cur ^ 1);
            __syncthreads();
        }
    }

    const float4 bv = *(const float4*)&bias[n0 + tn];
    #pragma unroll
    for (int i = 0; i < 4; i++) {
        int m    = m0 + tm + i;
        int ni   = m >> (2*LOG_OW);
        int rem  = m & (OHW-1);
        float* op = out + ((size_t)ni*OCt + n0 + tn)*OHW + rem;
        float b4[4] = {bv.x, bv.y, bv.z, bv.w};
        #pragma unroll
        for (int j = 0; j < 4; j++) {
            float v = acc[i][j] + b4[j];
            if (LRELU) v = v > 0.f ? v : 0.2f*v;
            op[(size_t)j*OHW] = v;
        }
    }
}

// ---------------- batchnorm: stats (double accum) then fused apply+lrelu ---
__global__ void bn_reduce_kernel(const float* __restrict__ x, const float* __restrict__ g,
                                 const float* __restrict__ be, int N, int C, int S) {
    int c = blockIdx.x;
    double s = 0.0, s2 = 0.0;
    int M = N*S;
    for (int j = threadIdx.x; j < M; j += blockDim.x) {
        int n = j / S, sp = j % S;
        float v = x[((size_t)n*C + c)*S + sp];
        s += (double)v; s2 += (double)v*(double)v;
    }
    __shared__ double sh[256], sh2[256];
    sh[threadIdx.x] = s; sh2[threadIdx.x] = s2; __syncthreads();
    for (int st = 128; st > 0; st >>= 1) {
        if (threadIdx.x < st) { sh[threadIdx.x] += sh[threadIdx.x+st]; sh2[threadIdx.x] += sh2[threadIdx.x+st]; }
        __syncthreads();
    }
    if (threadIdx.x == 0) {
        double mean = sh[0] / M;
        double var  = sh2[0] / M - mean*mean;
        double isd  = 1.0 / sqrt(var + 1e-5);
        float sc = (float)((double)g[c] * isd);
        g_bnscale[c] = sc;
        g_bnshift[c] = be[c] - (float)(mean * (double)sc);
    }
}

__global__ void bn_apply_kernel(float* __restrict__ x, int C, int S, int total) {
    for (int idx = blockIdx.x*blockDim.x + threadIdx.x; idx < total; idx += gridDim.x*blockDim.x) {
        int c = (idx / S) % C;
        float v = x[idx]*g_bnscale[c] + g_bnshift[c];
        x[idx] = v > 0.f ? v : 0.2f*v;
    }
}

// ---------------- conv5 (dot product per patch) + loss ----------------
__global__ void conv5_kernel(const float* __restrict__ in, const float* __restrict__ w,
                             const float* __restrict__ b5) {
    int n = blockIdx.x, tid = threadIdx.x;
    const float* ip = in + (size_t)n*8192;
    float s = 0.f;
    for (int i = tid; i < 8192; i += 256) s += ip[i]*w[i];
    __shared__ float sh[256];
    sh[tid] = s; __syncthreads();
    for (int st = 128; st > 0; st >>= 1) { if (tid < st) sh[tid] += sh[tid+st]; __syncthreads(); }
    if (tid == 0) g_logits[n] = sh[0] + b5[0];
}

__global__ void loss_kernel(float* __restrict__ out) {
    int tid = threadIdx.x;   // 64
    float x = -g_logits[tid];
    float sp = fmaxf(x, 0.f) + log1pf(expf(-fabsf(x)));
    __shared__ float sh[64];
    sh[tid] = sp; __syncthreads();
    for (int s = 32; s > 0; s >>= 1) { if (tid < s) sh[tid] += sh[tid+s]; __syncthreads(); }
    if (tid == 0) out[0] = sh[0] / 64.f;
}

// ---------------- launcher ----------------
extern "C" void kernel_launch(void* const* d_in, const int* in_sizes, int n_in,
                              void* d_out, int out_size) {
    const float* pred     = (const float*)d_in[0];
    const float* source   = (const float*)d_in[1];
    const int*   rand_sel = (const int*)d_in[2];
    const float* w1 = (const float*)d_in[3];  const float* b1 = (const float*)d_in[4];
    const float* w2 = (const float*)d_in[5];  const float* b2 = (const float*)d_in[6];
    const float* g2 = (const float*)d_in[7];  const float* be2= (const float*)d_in[8];
    const float* w3 = (const float*)d_in[9];  const float* b3 = (const float*)d_in[10];
    const float* g3 = (const float*)d_in[11]; const float* be3= (const float*)d_in[12];
    const float* w4 = (const float*)d_in[13]; const float* b4 = (const float*)d_in[14];
    const float* g4 = (const float*)d_in[15]; const float* be4= (const float*)d_in[16];
    const float* w5 = (const float*)d_in[17]; const float* b5 = (const float*)d_in[18];
    float* out = (float*)d_out;

    float *patches, *a1, *a2, *a3, *a4, *wT1, *wT2, *wT3, *wT4;
    cudaGetSymbolAddress((void**)&patches, g_patches);
    cudaGetSymbolAddress((void**)&a1, g_act1);
    cudaGetSymbolAddress((void**)&a2, g_act2);
    cudaGetSymbolAddress((void**)&a3, g_act3);
    cudaGetSymbolAddress((void**)&a4, g_act4);
    cudaGetSymbolAddress((void**)&wT1, g_wT1);
    cudaGetSymbolAddress((void**)&wT2, g_wT2);
    cudaGetSymbolAddress((void**)&wT3, g_wT3);
    cudaGetSymbolAddress((void**)&wT4, g_wT4);

    // 0. weight transposes (overlap with detector work in graph order anyway)
    wtrans_kernel<<<(48*64 + 255)/256, 256>>>(w1, wT1, 64, 48);
    wtrans_kernel<<<(1024*128 + 255)/256, 256>>>(w2, wT2, 128, 1024);
    wtrans_kernel<<<(2048*256 + 255)/256, 256>>>(w3, wT3, 256, 2048);
    wtrans_kernel<<<(4096*512 + 255)/256, 256>>>(w4, wT4, 512, 4096);
    // 1. detector mask
    detector_kernel<<<8192, 256>>>(source);
    // 2. 15x15 avg pool (separable)
    hpool_kernel<<<dim3(HH, BB), 256>>>();
    vpool_kernel<<<dim3(WW/32, HH/64, BB), 256>>>();
    // 3. exact per-image top-100 (radix select)
    topk_init_kernel<<<1, 256>>>();
    for (int d = 3; d >= 0; d--) {
        topk_hist_kernel<<<dim3(48, BB), 256>>>(d);
        topk_resolve_kernel<<<1, 256>>>(d);
    }
    topk_collect_kernel<<<dim3(48, BB), 256>>>();
    topk_final_kernel<<<BB, 128>>>();
    // 4. patch coords + gather
    coords_kernel<<<1, 64>>>(rand_sel);
    gather_kernel<<<(NPATCH*3*PS*PS + 255)/256, 256>>>(pred);
    // 5. discriminator (implicit GEMM)
    conv_gemm_kernel<3, 5, true ><<<dim3(1024, 1), 256>>>(patches, wT1, b1, a1, 48);
    conv_gemm_kernel<64, 4, false><<<dim3(256, 2), 256>>>(a1, wT2, b2, a2, 1024);
    bn_reduce_kernel<<<128, 256>>>(a2, g2, be2, NPATCH, 128, 16*16);
    bn_apply_kernel<<<1024, 256>>>(a2, 128, 16*16, NPATCH*128*16*16);
    conv_gemm_kernel<128, 3, false><<<dim3(64, 4), 256>>>(a2, wT3, b3, a3, 2048);
    bn_reduce_kernel<<<256, 256>>>(a3, g3, be3, NPATCH, 256, 8*8);
    bn_apply_kernel<<<512, 256>>>(a3, 256, 8*8, NPATCH*256*8*8);
    conv_gemm_kernel<256, 2, false><<<dim3(16, 8), 256>>>(a3, wT4, b4, a4, 4096);
    bn_reduce_kernel<<<512, 256>>>(a4, g4, be4, NPATCH, 512, 4*4);
    bn_apply_kernel<<<256, 256>>>(a4, 512, 4*4, NPATCH*512*4*4);
    conv5_kernel<<<NPATCH, 256>>>(a4, w5, b5);
    // 6. loss
    loss_kernel<<<1, 64>>>(out);
}